// round 9
// baseline (speedup 1.0000x reference)
#include <cuda_runtime.h>

#define NB   4
#define NT   4096
#define DIN  64
#define DM   256
#define BT   (NB*NT)
#define BLK  128                 // rows per block (chunk)
#define HALF 64
#define NCHB (NT/BLK)            // 32 chunks per batch
#define NBLK (BT/BLK)            // 128 blocks (one wave, co-resident)

typedef unsigned long long ull;

// -------- globals (zero-init; no allocation allowed) --------
__device__ float g_S[NBLK*DM];
__device__ float g_Zc[NBLK];
__device__ float g_Ac[NBLK];
__device__ int   g_flag[NBLK];
__device__ int   g_epoch;

__global__ void bump_epoch_kernel() { g_epoch = g_epoch + 1; }

// packed fp32x2 FMA (Blackwell; ptxas won't emit from C++)
static __device__ __forceinline__ void ffma2(ull &acc, ull a, ull b) {
    asm("fma.rn.f32x2 %0, %1, %2, %0;" : "+l"(acc) : "l"(a), "l"(b));
}
static __device__ __forceinline__ ull pack2(float lo, float hi) {
    ull r;
    asm("mov.b64 %0, {%1, %2};" : "=l"(r) : "f"(lo), "f"(hi));
    return r;
}

// -------- smem layout --------
#define XSS 68                        // x tile row stride (floats)
#define WP  129                       // W-pair tile row stride (ull)
#define HSS 264                       // h/prefix tile row stride (floats)
#define TAIL_OFF (128*HSS)            // floats
// tail: ds[128] sZl[128] sP[128] srZ[128] shS0[256] sC[512] sA[32] sZt[32] sAp[32] sScal[4]
#define GSMEM ((TAIL_OFF + 128*4 + 256 + 512 + 32*3 + 4)*4)

__global__ __launch_bounds__(512, 1)
void fused_kernel(const float* __restrict__ x, const float* __restrict__ tau,
                  const float* __restrict__ W, const float* __restrict__ bias,
                  const float* __restrict__ lamb, float* __restrict__ out)
{
    extern __shared__ float sm[];
    float* xs   = sm;                      // GEMM phase
    ull*   ws2  = (ull*)(sm + 128*XSS);
    float* wsf  = (float*)ws2;
    float* hs   = sm;                      // scan phase (overlays tiles)
    float* ds   = sm + TAIL_OFF;           // [128]
    float* sZl  = ds   + 128;              // [128] local Z prefix (per row)
    float* sP   = sZl  + 128;              // [128] decay prefix product (per row)
    float* srZ  = sP   + 128;              // [128] 1/Z_full per row
    float* shS0 = srZ  + 128;              // [256] half-0 end S
    float* sC   = shS0 + 256;              // [512] per-column carries (half0|half1)
    float* sA   = sC   + 512;              // [32]
    float* sZt  = sA   + 32;               // [32]
    float* sAp  = sZt  + 32;               // [32]
    float* sScal= sAp  + 32;               // [0]=cZ

    __shared__ int s_epoch;

    const int t    = threadIdx.x;
    const int blk  = blockIdx.x;
    const int row0 = blk * BLK;
    const int kk   = blk & (NCHB-1);
    const int base = blk - kk;
    const int half = t >> 8;
    const int m    = t & 255;

    if (t == 0) s_epoch = g_epoch;

    // ---- decays (disjoint smem region; overlaps tile loads) ----
    if (t < BLK) {
        float lam = fmaxf(__ldg(&lamb[0]), 0.0f);
        ds[t] = __expf(-lam * __ldg(&tau[row0 + t]));
    }

    // ---- GEMM tile loads ----
    #pragma unroll
    for (int li = 0; li < 4; li++) {
        int idx = t + 512*li;
        int r = idx >> 4;
        int q = idx & 15;
        *(float4*)&xs[r*XSS + 4*q] = *(const float4*)&x[(size_t)(row0 + r)*DIN + 4*q];
    }
    // W transposed fill, conflict-free STS: wsf[k*2*WP + c] = W[c][k]
    {
        const int cW = t & 255;
        const int kh = (t >> 8) * 32;
        const float* wrow = W + (size_t)cW*DIN + kh;
        #pragma unroll
        for (int j4 = 0; j4 < 8; j4++) {
            float4 wv = *(const float4*)&wrow[4*j4];
            int k = kh + 4*j4;
            wsf[(k+0)*2*WP + cW] = wv.x;
            wsf[(k+1)*2*WP + cW] = wv.y;
            wsf[(k+2)*2*WP + cW] = wv.z;
            wsf[(k+3)*2*WP + cW] = wv.w;
        }
    }
    __syncthreads();

    // ---- GEMM: 8 rows x 4 col-pairs / thread, f32x2 over col pairs ----
    const int r0 = t >> 5;
    const int c0 = t & 31;

    ull acc2[8][4];
    #pragma unroll
    for (int i = 0; i < 8; i++)
        #pragma unroll
        for (int j = 0; j < 4; j++) acc2[i][j] = 0ULL;

    #pragma unroll 4
    for (int k = 0; k < DIN; k++) {
        ull wv[4];
        #pragma unroll
        for (int j = 0; j < 4; j++)
            wv[j] = ws2[(size_t)k*WP + c0 + 32*j];
        #pragma unroll
        for (int i = 0; i < 8; i++) {
            float xv = xs[(r0 + 16*i)*XSS + k];
            ull xx = pack2(xv, xv);
            #pragma unroll
            for (int j = 0; j < 4; j++)
                ffma2(acc2[i][j], xx, wv[j]);
        }
    }
    __syncthreads();   // tiles dead -> h tile

    // ---- epilogue: +bias, elu -> smem h ----
    #pragma unroll
    for (int j = 0; j < 4; j++) {
        int p = c0 + 32*j;
        float2 bj = *(const float2*)&bias[2*p];
        #pragma unroll
        for (int i = 0; i < 8; i++) {
            int r = r0 + 16*i;
            ull a = acc2[i][j];
            float v0 = __uint_as_float((unsigned)a)         + bj.x;
            float v1 = __uint_as_float((unsigned)(a >> 32)) + bj.y;
            v0 = (v0 > 0.0f) ? v0 : (__expf(v0) - 1.0f);
            v1 = (v1 > 0.0f) ? v1 : (__expf(v1) - 1.0f);
            *(float2*)&hs[r*HSS + 2*p] = make_float2(v0, v1);
        }
    }
    __syncthreads();

    // ---- local scan with prefix stored in place ----
    const int i0 = half * HALF;
    float S = 0.0f, Z = 0.0f, P = 1.0f;
    #pragma unroll 8
    for (int i = 0; i < HALF; i++) {
        int r = i0 + i;
        float d = ds[r];
        S = fmaf(S, d, hs[r*HSS + m]);
        Z = fmaf(Z, d, 1.0f);
        P *= d;
        hs[r*HSS + m] = S;                 // prefix back in place
        if (m == 0) { sZl[r] = Z; sP[r] = P; }
    }
    if (half == 0) shS0[m] = S;
    __syncthreads();

    // ---- half-1 publishes combined block aggregate ----
    const int e = s_epoch;
    if (half == 1) {
        float A1 = P;
        g_S[(size_t)blk*DM + m] = fmaf(shS0[m], A1, S);
        if (m == 0) {
            g_Zc[blk] = fmaf(sZl[HALF-1], A1, Z);
            g_Ac[blk] = sP[HALF-1] * A1;
        }
        __threadfence();
    }
    __syncthreads();
    if (t == 0) *(volatile int*)&g_flag[blk] = e;   // release

    // ---- parallel lookback ----
    float cS = 0.0f, cZ = 0.0f;
    if (kk > 0) {
        int ok;
        do {
            ok = (t < kk) ? (*(volatile int*)&g_flag[base + t] == e) : 1;
        } while (!__syncthreads_and(ok));
        __threadfence();   // acquire

        if (t < kk) { sA[t] = g_Ac[base + t]; sZt[t] = g_Zc[base + t]; }
        __syncthreads();
        if (t == 0) {
            float Ap = 1.0f, z = 0.0f;
            for (int j = kk - 1; j >= 0; j--) {
                sAp[j] = Ap;
                z = fmaf(Ap, sZt[j], z);
                Ap *= sA[j];
            }
            sScal[0] = z;
        }
        __syncthreads();

        const float* gsb = g_S + (size_t)base*DM + m;
        #pragma unroll 4
        for (int j = 0; j < kk; j++)
            cS = fmaf(sAp[j], __ldg(&gsb[(size_t)j*DM]), cS);
        cZ = sScal[0];
    }

    // ---- per-column carries + per-row reciprocal Z ----
    if (t < 256) sC[t] = cS;                                  // half-0 carry
    else         sC[256 + m] = fmaf(sP[HALF-1], cS, shS0[m]); // half-1 carry
    if (t < BLK) {
        float CZh = (t < HALF) ? cZ : fmaf(sP[HALF-1], cZ, sZl[HALF-1]);
        float Zf  = fmaf(sP[t], CZh, sZl[t]);
        srZ[t] = __frcp_rn(Zf);
    }
    __syncthreads();

    // ---- chain-free vectorized output: out = (Sloc + P_i*C) * rZ_i ----
    {
        const int cg = t & 63;          // columns 4cg..4cg+3
        const int rl = t >> 6;          // 0..7 (warp-uniform)
        #pragma unroll
        for (int it = 0; it < 16; it++) {
            int i = rl + 8*it;
            float4 s4 = *(const float4*)&hs[i*HSS + 4*cg];
            float4 c4 = *(const float4*)&sC[((i >> 6) << 8) + 4*cg];
            float Pi = sP[i];
            float rz = srZ[i];
            float4 o;
            o.x = fmaf(Pi, c4.x, s4.x) * rz;
            o.y = fmaf(Pi, c4.y, s4.y) * rz;
            o.z = fmaf(Pi, c4.z, s4.z) * rz;
            o.w = fmaf(Pi, c4.w, s4.w) * rz;
            *(float4*)&out[(size_t)(row0 + i)*DM + 4*cg] = o;
        }
    }
}

// -------- launch --------
extern "C" void kernel_launch(void* const* d_in, const int* in_sizes, int n_in,
                              void* d_out, int out_size)
{
    const float* x    = (const float*)d_in[0];
    const float* tau  = (const float*)d_in[1];
    const float* W    = (const float*)d_in[2];
    const float* bias = (const float*)d_in[3];
    const float* lamb = (const float*)d_in[4];
    // beta (d_in[5]) cancels in softmax (constant per row)
    float* out = (float*)d_out;

    cudaFuncSetAttribute(fused_kernel,
                         cudaFuncAttributeMaxDynamicSharedMemorySize, GSMEM);

    bump_epoch_kernel<<<1, 1>>>();
    fused_kernel<<<NBLK, 512, GSMEM>>>(x, tau, W, bias, lamb, out);
}

// round 12
// speedup vs baseline: 1.0169x; 1.0169x over previous
#include <cuda_runtime.h>

#define NB   4
#define NT   4096
#define DIN  64
#define DM   256
#define BT   (NB*NT)
#define BLK  128                 // rows per block (chunk)
#define HALF 64
#define NCHB (NT/BLK)            // 32 chunks per batch
#define NBLK (BT/BLK)            // 128 blocks (one wave, co-resident)

typedef unsigned long long ull;

// -------- globals (no allocation allowed) --------
__device__ float g_S[NBLK*DM];
__device__ float g_Zc[NBLK];
__device__ float g_Ac[NBLK];
__device__ int   g_flag[NBLK];
__device__ int   g_epoch;

__global__ void bump_epoch_kernel() { g_epoch = g_epoch + 1; }

// packed fp32x2 FMA (Blackwell; ptxas won't emit from C++)
static __device__ __forceinline__ void ffma2(ull &acc, ull a, ull b) {
    asm("fma.rn.f32x2 %0, %1, %2, %0;" : "+l"(acc) : "l"(a), "l"(b));
}
static __device__ __forceinline__ ull pack2(float lo, float hi) {
    ull r;
    asm("mov.b64 %0, {%1, %2};" : "=l"(r) : "f"(lo), "f"(hi));
    return r;
}

// -------- smem layout (GEMM tiles overlaid by h tile) --------
#define XSS 68                        // x tile row stride (floats)
#define WP  129                       // W-pair tile row stride (ull)
#define HSS 264                       // h tile row stride (floats)
// after h tile: ds[128], shS0[256], sA[32], sZ[32], sAp[32], ssc[4]
#define GSMEM (128*HSS*4 + (128 + 256 + 32 + 32 + 32 + 4)*4)

__global__ __launch_bounds__(512, 1)
void fused_kernel(const float* __restrict__ x, const float* __restrict__ tau,
                  const float* __restrict__ W, const float* __restrict__ bias,
                  const float* __restrict__ lamb, float* __restrict__ out)
{
    extern __shared__ float sm[];
    float* xs   = sm;                     // GEMM phase
    ull*   ws2  = (ull*)(sm + 128*XSS);
    float* wsf  = (float*)ws2;
    float* hs   = sm;                     // scan phase (overlays tiles)
    float* ds   = sm + 128*HSS;           // [128] decays
    float* shS0 = ds + 128;               // [256] half-0 aggregate S
    float* sA   = shS0 + 256;             // [32] predecessor A
    float* sZ   = sA + 32;                // [32] predecessor Z
    float* sAp  = sZ + 32;                // [32] suffix products
    float* ssc  = sAp + 32;               // [0]=Z0 [1]=A0 [2]=cZ

    __shared__ int s_epoch;

    const int t    = threadIdx.x;
    const int blk  = blockIdx.x;
    const int row0 = blk * BLK;
    const int kk   = blk & (NCHB-1);
    const int base = blk - kk;
    const int half = t >> 8;             // 0/1
    const int m    = t & 255;            // column

    if (t == 0) s_epoch = g_epoch;

    // ---- decays first (region disjoint from GEMM tiles; hides under tile loads)
    if (t < BLK) {
        float lam = fmaxf(__ldg(&lamb[0]), 0.0f);
        ds[t] = __expf(-lam * __ldg(&tau[row0 + t]));
    }

    // ---- GEMM tile loads ----
    #pragma unroll
    for (int li = 0; li < 4; li++) {
        int idx = t + 512*li;
        int r = idx >> 4;
        int q = idx & 15;
        *(float4*)&xs[r*XSS + 4*q] = *(const float4*)&x[(size_t)(row0 + r)*DIN + 4*q];
    }
    #pragma unroll
    for (int li = 0; li < 8; li++) {
        int idx = t + 512*li;
        int c = idx >> 4;
        int q = idx & 15;
        float4 wv = *(const float4*)&W[(size_t)c*DIN + 4*q];
        int p = c >> 1, wd = c & 1;
        wsf[((4*q+0)*WP + p)*2 + wd] = wv.x;
        wsf[((4*q+1)*WP + p)*2 + wd] = wv.y;
        wsf[((4*q+2)*WP + p)*2 + wd] = wv.z;
        wsf[((4*q+3)*WP + p)*2 + wd] = wv.w;
    }
    __syncthreads();

    // ---- GEMM: 8 rows x 4 col-pairs / thread, f32x2 over col pairs ----
    // k chunked by 4: x rows prefetched via broadcast LDS.128 (float4)
    const int r0 = t >> 5;
    const int c0 = t & 31;

    ull acc2[8][4];
    #pragma unroll
    for (int i = 0; i < 8; i++)
        #pragma unroll
        for (int j = 0; j < 4; j++) acc2[i][j] = 0ULL;

    #pragma unroll
    for (int kc = 0; kc < 16; kc++) {
        float4 xv[8];
        #pragma unroll
        for (int i = 0; i < 8; i++)
            xv[i] = *(const float4*)&xs[(r0 + 16*i)*XSS + 4*kc];   // broadcast 16B
        #pragma unroll
        for (int kq = 0; kq < 4; kq++) {
            const int k = 4*kc + kq;
            ull wv[4];
            #pragma unroll
            for (int j = 0; j < 4; j++)
                wv[j] = ws2[(size_t)k*WP + c0 + 32*j];
            #pragma unroll
            for (int i = 0; i < 8; i++) {
                float xk = (kq == 0) ? xv[i].x : (kq == 1) ? xv[i].y
                         : (kq == 2) ? xv[i].z : xv[i].w;
                ull xx = pack2(xk, xk);
                #pragma unroll
                for (int j = 0; j < 4; j++)
                    ffma2(acc2[i][j], xx, wv[j]);
            }
        }
    }
    __syncthreads();   // tiles dead -> h tile

    // ---- epilogue: +bias, elu -> smem h ----
    #pragma unroll
    for (int j = 0; j < 4; j++) {
        int p = c0 + 32*j;
        float2 bj = *(const float2*)&bias[2*p];
        #pragma unroll
        for (int i = 0; i < 8; i++) {
            int r = r0 + 16*i;
            ull a = acc2[i][j];
            float v0 = __uint_as_float((unsigned)a)         + bj.x;
            float v1 = __uint_as_float((unsigned)(a >> 32)) + bj.y;
            v0 = (v0 > 0.0f) ? v0 : (__expf(v0) - 1.0f);
            v1 = (v1 > 0.0f) ? v1 : (__expf(v1) - 1.0f);
            *(float2*)&hs[r*HSS + 2*p] = make_float2(v0, v1);
        }
    }
    __syncthreads();

    // ---- local scan, split across halves (64 rows each, all 512 threads) ----
    const int i0 = half * HALF;
    float S = 0.0f, Z = 0.0f, A = 1.0f;
    #pragma unroll 8
    for (int i = 0; i < HALF; i++) {
        float d = ds[i0 + i];
        S = fmaf(S, d, hs[(i0 + i)*HSS + m]);
        Z = fmaf(Z, d, 1.0f);
        A *= d;
    }
    if (half == 0) {
        shS0[m] = S;
        if (m == 0) { ssc[0] = Z; ssc[1] = A; }
    }
    __syncthreads();

    // ---- half-1 publishes combined block aggregate ----
    const int e = s_epoch;
    if (half == 1) {
        g_S[(size_t)blk*DM + m] = fmaf(shS0[m], A, S);
        if (m == 0) {
            g_Zc[blk] = fmaf(ssc[0], A, Z);
            g_Ac[blk] = ssc[1] * A;
        }
        __threadfence();
    }
    __syncthreads();
    if (t == 0) *(volatile int*)&g_flag[blk] = e;   // release

    // ---- parallel lookback ----
    float cS = 0.0f, cZ = 0.0f;
    if (kk > 0) {
        int ok;
        do {
            ok = (t < kk) ? (*(volatile int*)&g_flag[base + t] == e) : 1;
        } while (!__syncthreads_and(ok));
        __threadfence();   // acquire

        if (t < kk) { sA[t] = g_Ac[base + t]; sZ[t] = g_Zc[base + t]; }
        __syncthreads();
        if (t == 0) {       // suffix products + scalar cZ (<=31 fmas)
            float Ap = 1.0f, z = 0.0f;
            for (int j = kk - 1; j >= 0; j--) {
                sAp[j] = Ap;
                z = fmaf(Ap, sZ[j], z);
                Ap *= sA[j];
            }
            ssc[2] = z;
        }
        __syncthreads();

        // independent loads across j -> fully pipelined
        const float* gsb = g_S + (size_t)base*DM + m;
        #pragma unroll 4
        for (int j = 0; j < kk; j++)
            cS = fmaf(sAp[j], __ldg(&gsb[(size_t)j*DM]), cS);
        cZ = ssc[2];
    }

    // ---- finalize per half, write out ----
    float Sf, Zf;
    if (half == 0) { Sf = cS; Zf = cZ; }
    else {
        float A0 = ssc[1];
        Sf = fmaf(cS, A0, shS0[m]);
        Zf = fmaf(cZ, A0, ssc[0]);
    }
    float* op = out + (size_t)(row0 + i0)*DM + m;
    #pragma unroll 8
    for (int i = 0; i < HALF; i++) {
        float d = ds[i0 + i];
        Sf = fmaf(Sf, d, hs[(i0 + i)*HSS + m]);
        Zf = fmaf(Zf, d, 1.0f);
        op[(size_t)i*DM] = __fdividef(Sf, Zf);
    }
}

// -------- launch --------
extern "C" void kernel_launch(void* const* d_in, const int* in_sizes, int n_in,
                              void* d_out, int out_size)
{
    const float* x    = (const float*)d_in[0];
    const float* tau  = (const float*)d_in[1];
    const float* W    = (const float*)d_in[2];
    const float* bias = (const float*)d_in[3];
    const float* lamb = (const float*)d_in[4];
    // beta (d_in[5]) cancels in softmax (constant per row)
    float* out = (float*)d_out;

    cudaFuncSetAttribute(fused_kernel,
                         cudaFuncAttributeMaxDynamicSharedMemorySize, GSMEM);

    bump_epoch_kernel<<<1, 1>>>();
    fused_kernel<<<NBLK, 512, GSMEM>>>(x, tau, W, bias, lamb, out);
}

// round 13
// speedup vs baseline: 1.0623x; 1.0447x over previous
#include <cuda_runtime.h>

#define NB   4
#define NT   4096
#define DIN  64
#define DM   256
#define BT   (NB*NT)
#define BLK  128                 // rows per block (chunk)
#define HALF 64
#define NCHB (NT/BLK)            // 32 chunks per batch
#define NBLK (BT/BLK)            // 128 blocks (one wave, co-resident)

typedef unsigned long long ull;

// -------- globals (no allocation allowed) --------
__device__ float g_S[NBLK*DM];
__device__ float g_Zc[NBLK];
__device__ float g_Ac[NBLK];
__device__ int   g_flag[NBLK];
__device__ int   g_epoch;

__global__ void bump_epoch_kernel() { g_epoch = g_epoch + 1; }

// packed fp32x2 FMA (Blackwell; ptxas won't emit from C++)
static __device__ __forceinline__ void ffma2(ull &acc, ull a, ull b) {
    asm("fma.rn.f32x2 %0, %1, %2, %0;" : "+l"(acc) : "l"(a), "l"(b));
}
static __device__ __forceinline__ ull pack2(float lo, float hi) {
    ull r;
    asm("mov.b64 %0, {%1, %2};" : "=l"(r) : "f"(lo), "f"(hi));
    return r;
}

// -------- smem layout (GEMM tiles overlaid by h tile) --------
#define XSS 68                        // x tile row stride (floats)
#define WP  129                       // W-pair tile row stride (ull)
#define HSS 264                       // h tile row stride (floats)
// tail: ds[128] shS0[256] sA[32] sZt[32] sAp[32] sScal[4] sZl[128] sP[128] srZ[128]
#define GSMEM (128*HSS*4 + (128 + 256 + 32 + 32 + 32 + 4 + 128 + 128 + 128)*4)

__global__ __launch_bounds__(512, 1)
void fused_kernel(const float* __restrict__ x, const float* __restrict__ tau,
                  const float* __restrict__ W, const float* __restrict__ bias,
                  const float* __restrict__ lamb, float* __restrict__ out)
{
    extern __shared__ float sm[];
    float* xs    = sm;                     // GEMM phase
    ull*   ws2   = (ull*)(sm + 128*XSS);
    float* wsf   = (float*)ws2;
    float* hs    = sm;                     // scan phase (overlays tiles)
    float* ds    = sm + 128*HSS;           // [128] decays
    float* shS0  = ds    + 128;            // [256] half-0 end S
    float* sA    = shS0  + 256;            // [32] predecessor A
    float* sZt   = sA    + 32;             // [32] predecessor Z
    float* sAp   = sZt   + 32;             // [32] suffix products
    float* sScal = sAp   + 32;             // [0]=cZ
    float* sZl   = sScal + 4;              // [128] local Z per row
    float* sP    = sZl   + 128;            // [128] decay prefix product per row
    float* srZ   = sP    + 128;            // [128] 1/Z_full per row

    __shared__ int s_epoch;

    const int t    = threadIdx.x;
    const int blk  = blockIdx.x;
    const int row0 = blk * BLK;
    const int kk   = blk & (NCHB-1);
    const int base = blk - kk;
    const int half = t >> 8;             // 0/1
    const int m    = t & 255;            // column

    if (t == 0) s_epoch = g_epoch;

    // ---- decays first (region disjoint from GEMM tiles; hides under tile loads)
    if (t < BLK) {
        float lam = fmaxf(__ldg(&lamb[0]), 0.0f);
        ds[t] = __expf(-lam * __ldg(&tau[row0 + t]));
    }

    // ---- GEMM tile loads (R6 form) ----
    #pragma unroll
    for (int li = 0; li < 4; li++) {
        int idx = t + 512*li;
        int r = idx >> 4;
        int q = idx & 15;
        *(float4*)&xs[r*XSS + 4*q] = *(const float4*)&x[(size_t)(row0 + r)*DIN + 4*q];
    }
    #pragma unroll
    for (int li = 0; li < 8; li++) {
        int idx = t + 512*li;
        int c = idx >> 4;
        int q = idx & 15;
        float4 wv = *(const float4*)&W[(size_t)c*DIN + 4*q];
        int p = c >> 1, wd = c & 1;
        wsf[((4*q+0)*WP + p)*2 + wd] = wv.x;
        wsf[((4*q+1)*WP + p)*2 + wd] = wv.y;
        wsf[((4*q+2)*WP + p)*2 + wd] = wv.z;
        wsf[((4*q+3)*WP + p)*2 + wd] = wv.w;
    }
    __syncthreads();

    // ---- GEMM: 8 rows x 4 col-pairs / thread, f32x2 over col pairs (R6 form) ----
    const int r0 = t >> 5;
    const int c0 = t & 31;

    ull acc2[8][4];
    #pragma unroll
    for (int i = 0; i < 8; i++)
        #pragma unroll
        for (int j = 0; j < 4; j++) acc2[i][j] = 0ULL;

    #pragma unroll 4
    for (int k = 0; k < DIN; k++) {
        ull wv[4];
        #pragma unroll
        for (int j = 0; j < 4; j++)
            wv[j] = ws2[(size_t)k*WP + c0 + 32*j];
        #pragma unroll
        for (int i = 0; i < 8; i++) {
            float xv = xs[(r0 + 16*i)*XSS + k];   // warp-broadcast
            ull xx = pack2(xv, xv);
            #pragma unroll
            for (int j = 0; j < 4; j++)
                ffma2(acc2[i][j], xx, wv[j]);
        }
    }
    __syncthreads();   // tiles dead -> h tile

    // ---- epilogue: +bias, elu -> smem h ----
    #pragma unroll
    for (int j = 0; j < 4; j++) {
        int p = c0 + 32*j;
        float2 bj = *(const float2*)&bias[2*p];
        #pragma unroll
        for (int i = 0; i < 8; i++) {
            int r = r0 + 16*i;
            ull a = acc2[i][j];
            float v0 = __uint_as_float((unsigned)a)         + bj.x;
            float v1 = __uint_as_float((unsigned)(a >> 32)) + bj.y;
            v0 = (v0 > 0.0f) ? v0 : (__expf(v0) - 1.0f);
            v1 = (v1 > 0.0f) ? v1 : (__expf(v1) - 1.0f);
            *(float2*)&hs[r*HSS + 2*p] = make_float2(v0, v1);
        }
    }
    __syncthreads();

    // ---- local scan (S chain only; Z factored out), halves of 64 rows ----
    const int i0 = half * HALF;
    float S = 0.0f, A = 1.0f;
    #pragma unroll 8
    for (int i = 0; i < HALF; i++) {
        float d = ds[i0 + i];
        S = fmaf(S, d, hs[(i0 + i)*HSS + m]);
        A *= d;
    }
    if (half == 0) shS0[m] = S;

    // ---- warp 0: row-wise Z and prefix-product P via shfl scan ----
    if (t < 32) {
        float d0 = ds[4*t+0], d1 = ds[4*t+1], d2 = ds[4*t+2], d3 = ds[4*t+3];
        float Aseg = d0*d1*d2*d3;
        float z = 1.0f;                    // z after row 4t (z_in = 0)
        z = fmaf(d1, z, 1.0f);
        z = fmaf(d2, z, 1.0f);
        z = fmaf(d3, z, 1.0f);             // local 4-row Z
        float Ai = Aseg, Zi = z;
        #pragma unroll
        for (int off = 1; off < 32; off <<= 1) {
            float Al = __shfl_up_sync(0xffffffffu, Ai, off);
            float Zl_ = __shfl_up_sync(0xffffffffu, Zi, off);
            if (t >= off) {
                Zi = fmaf(Zl_, Ai, Zi);    // left composed with right (old right A)
                Ai = Al * Ai;
            }
        }
        float Aex = __shfl_up_sync(0xffffffffu, Ai, 1);
        float Zex = __shfl_up_sync(0xffffffffu, Zi, 1);
        if (t == 0) { Aex = 1.0f; Zex = 0.0f; }
        float P = Aex, zz = Zex;
        zz = fmaf(d0, zz, 1.0f); P *= d0; sZl[4*t+0] = zz; sP[4*t+0] = P;
        zz = fmaf(d1, zz, 1.0f); P *= d1; sZl[4*t+1] = zz; sP[4*t+1] = P;
        zz = fmaf(d2, zz, 1.0f); P *= d2; sZl[4*t+2] = zz; sP[4*t+2] = P;
        zz = fmaf(d3, zz, 1.0f); P *= d3; sZl[4*t+3] = zz; sP[4*t+3] = P;
    }
    __syncthreads();

    // ---- half-1 publishes combined block aggregate ----
    const int e = s_epoch;
    if (half == 1) {
        g_S[(size_t)blk*DM + m] = fmaf(shS0[m], A, S);   // A = prod d[64..127]
        if (m == 0) {
            g_Zc[blk] = sZl[BLK-1];
            g_Ac[blk] = sP[BLK-1];
        }
        __threadfence();
    }
    __syncthreads();
    if (t == 0) *(volatile int*)&g_flag[blk] = e;   // release

    // ---- parallel lookback ----
    float cS = 0.0f, cZ = 0.0f;
    if (kk > 0) {
        int ok;
        do {
            ok = (t < kk) ? (*(volatile int*)&g_flag[base + t] == e) : 1;
        } while (!__syncthreads_and(ok));
        __threadfence();   // acquire

        if (t < kk) { sA[t] = g_Ac[base + t]; sZt[t] = g_Zc[base + t]; }
        __syncthreads();
        if (t == 0) {       // suffix products + scalar cZ (<=31 fmas)
            float Ap = 1.0f, z = 0.0f;
            for (int j = kk - 1; j >= 0; j--) {
                sAp[j] = Ap;
                z = fmaf(Ap, sZt[j], z);
                Ap *= sA[j];
            }
            sScal[0] = z;
        }
        __syncthreads();

        // independent loads across j -> fully pipelined
        const float* gsb = g_S + (size_t)base*DM + m;
        #pragma unroll 4
        for (int j = 0; j < kk; j++)
            cS = fmaf(sAp[j], __ldg(&gsb[(size_t)j*DM]), cS);
        cZ = sScal[0];
    }

    // ---- per-row reciprocal of full Z (128 rcps total) ----
    if (t < BLK) srZ[t] = __frcp_rn(fmaf(sP[t], cZ, sZl[t]));
    __syncthreads();

    // ---- finalize per half: S chain only, out = Sf * rZ[i] ----
    float Sf = (half == 0) ? cS : fmaf(cS, sP[HALF-1], shS0[m]);
    float* op = out + (size_t)(row0 + i0)*DM + m;
    #pragma unroll 8
    for (int i = 0; i < HALF; i++) {
        float d = ds[i0 + i];
        Sf = fmaf(Sf, d, hs[(i0 + i)*HSS + m]);
        op[(size_t)i*DM] = Sf * srZ[i0 + i];
    }
}

// -------- launch --------
extern "C" void kernel_launch(void* const* d_in, const int* in_sizes, int n_in,
                              void* d_out, int out_size)
{
    const float* x    = (const float*)d_in[0];
    const float* tau  = (const float*)d_in[1];
    const float* W    = (const float*)d_in[2];
    const float* bias = (const float*)d_in[3];
    const float* lamb = (const float*)d_in[4];
    // beta (d_in[5]) cancels in softmax (constant per row)
    float* out = (float*)d_out;

    cudaFuncSetAttribute(fused_kernel,
                         cudaFuncAttributeMaxDynamicSharedMemorySize, GSMEM);

    bump_epoch_kernel<<<1, 1>>>();
    fused_kernel<<<NBLK, 512, GSMEM>>>(x, tau, W, bias, lamb, out);
}